// round 11
// baseline (speedup 1.0000x reference)
#include <cuda_runtime.h>
#include <math.h>

// Quaternion LSTM: T=128, B=64, F=512, H=1024.
// Round 11: fuse x@W into the persistent recurrence (kills gemm_in + g_G),
// per-SM balanced static tiles (1024 tiles of 64x32x(128U+64x)) using the
// classic-placement pairing law (bid and bid+148 share an SM).
// Launch order puts recurrence 4th so ncu finally captures it.

#define T_ 128
#define B_ 64
#define Fdim 512
#define H_ 1024
#define N4 (4 * H_)          // 4096
#define FO (Fdim + 1)        // 513
#define SPLITK 8
#define NCTA 256
#define NSM 148

// ---- scratch (static device globals: allocation-free) ----
__device__ float g_Wcat[(size_t)Fdim * N4];            //  8 MB
__device__ float g_bias4[N4];
__device__ float g_Ucat[(size_t)H_ * N4];              // 16 MB
__device__ float g_preK[(size_t)SPLITK * B_ * N4];     //  8 MB
__device__ float g_h[B_ * H_];
__device__ float g_c[B_ * H_];
__device__ float g_Hbuf[(size_t)T_ * B_ * H_];         // 32 MB
__device__ unsigned g_cnt;
__device__ volatile unsigned g_gen;

__device__ const float c_sgn[16] = {
    1.f, -1.f, -1.f, -1.f,
    1.f,  1.f, -1.f,  1.f,
    1.f,  1.f,  1.f, -1.f,
    1.f, -1.f,  1.f,  1.f
};

// ---------------- builds ----------------
__global__ void build_W(const float* __restrict__ wf, const float* __restrict__ wi,
                        const float* __restrict__ wo, const float* __restrict__ wc) {
    int idx = blockIdx.x * blockDim.x + threadIdx.x;
    if (idx >= Fdim * N4) return;
    int row  = idx / N4;
    int col  = idx % N4;
    int gate = col / H_;
    int cj   = col % H_;
    int rb = row / (Fdim / 4), a = row % (Fdim / 4);
    int cb = cj / (H_ / 4),    b = cj % (H_ / 4);
    const float* w = (gate == 0) ? wf : (gate == 1) ? wi : (gate == 2) ? wo : wc;
    g_Wcat[idx] = c_sgn[cb * 4 + rb] *
                  w[((size_t)(rb ^ cb) * (Fdim / 4) + a) * (H_ / 4) + b];
}

__global__ void build_U(const float* __restrict__ uf, const float* __restrict__ ui,
                        const float* __restrict__ uo, const float* __restrict__ uc) {
    int idx = blockIdx.x * blockDim.x + threadIdx.x;
    if (idx >= H_ * N4) return;
    int row  = idx / N4;
    int col  = idx % N4;
    int gate = col / H_;
    int cj   = col % H_;
    int rb = row / (H_ / 4), a = row % (H_ / 4);
    int cb = cj / (H_ / 4),  b = cj % (H_ / 4);
    const float* w = (gate == 0) ? uf : (gate == 1) ? ui : (gate == 2) ? uo : uc;
    g_Ucat[idx] = c_sgn[cb * 4 + rb] *
                  w[((size_t)(rb ^ cb) * (H_ / 4) + a) * (H_ / 4) + b];
}

// init state + bias (3rd launch)
__global__ void init_misc(const float* __restrict__ bf, const float* __restrict__ bi,
                          const float* __restrict__ bo, const float* __restrict__ bc) {
    int idx = blockIdx.x * blockDim.x + threadIdx.x;
    if (idx < B_ * H_) { g_h[idx] = 0.f; g_c[idx] = 0.f; }
    if (idx < N4) {
        int gate = idx / H_, j = idx % H_;
        const float* b = (gate == 0) ? bf : (gate == 1) ? bi : (gate == 2) ? bo : bc;
        g_bias4[idx] = b[j];
    }
    if (idx == 0) { g_cnt = 0; g_gen = 0; }
}

// ---------------- generic fp32 GEMM (output projection only) ----------------
__global__ __launch_bounds__(256) void gemm_out(const float* __restrict__ fw,
                                                const float* __restrict__ fb,
                                                float* __restrict__ out) {
    const float* A = g_Hbuf;
    const int M = T_ * B_, N = FO, K = H_;
    const int BM = 128, BN = 128, BK = 16;
    __shared__ float As[BK][BM];
    __shared__ float Bs[BK][BN];
    int tid = threadIdx.x;
    int tx = tid % 16, ty = tid / 16;
    int rowBase = blockIdx.y * BM;
    int colBase = blockIdx.x * BN;
    float acc[8][8];
    #pragma unroll
    for (int i = 0; i < 8; i++)
        #pragma unroll
        for (int j = 0; j < 8; j++) acc[i][j] = 0.f;

    for (int k0 = 0; k0 < K; k0 += BK) {
        #pragma unroll
        for (int i = 0; i < 2; i++) {
            int lin = tid + i * 256;
            int r = lin >> 2, c4 = (lin & 3) * 4;
            float4 v = *reinterpret_cast<const float4*>(
                &A[(size_t)(rowBase + r) * K + k0 + c4]);
            As[c4 + 0][r] = v.x;
            As[c4 + 1][r] = v.y;
            As[c4 + 2][r] = v.z;
            As[c4 + 3][r] = v.w;
        }
        #pragma unroll
        for (int i = 0; i < 8; i++) {
            int lin = tid + i * 256;
            int kk = lin >> 7, n = lin & 127;
            int gn = colBase + n;
            float v = 0.f;
            if (gn < N) v = fw[(size_t)(k0 + kk) * N + gn];
            Bs[kk][n] = v;
        }
        __syncthreads();
        #pragma unroll
        for (int kk = 0; kk < BK; kk++) {
            float a[8], b[8];
            float4 a0 = *reinterpret_cast<const float4*>(&As[kk][ty * 8]);
            float4 a1 = *reinterpret_cast<const float4*>(&As[kk][ty * 8 + 4]);
            float4 b0 = *reinterpret_cast<const float4*>(&Bs[kk][tx * 8]);
            float4 b1 = *reinterpret_cast<const float4*>(&Bs[kk][tx * 8 + 4]);
            a[0]=a0.x; a[1]=a0.y; a[2]=a0.z; a[3]=a0.w;
            a[4]=a1.x; a[5]=a1.y; a[6]=a1.z; a[7]=a1.w;
            b[0]=b0.x; b[1]=b0.y; b[2]=b0.z; b[3]=b0.w;
            b[4]=b1.x; b[5]=b1.y; b[6]=b1.z; b[7]=b1.w;
            #pragma unroll
            for (int i = 0; i < 8; i++)
                #pragma unroll
                for (int j = 0; j < 8; j++)
                    acc[i][j] += a[i] * b[j];
        }
        __syncthreads();
    }
    #pragma unroll
    for (int i = 0; i < 8; i++) {
        int gm = rowBase + ty * 8 + i;
        if (gm >= M) continue;
        #pragma unroll
        for (int j = 0; j < 8; j++) {
            int gn = colBase + tx * 8 + j;
            if (gn >= N) continue;
            out[(size_t)gm * N + gn] = acc[i][j] + fb[gn];
        }
    }
}

// ---------------- grid barrier (R7-proven) ----------------
__device__ __forceinline__ void grid_barrier() {
    __syncthreads();
    __threadfence();
    if (threadIdx.x == 0) {
        unsigned gen = g_gen;
        unsigned prev = atomicAdd(&g_cnt, 1u);
        if (prev == NCTA - 1) {
            g_cnt = 0;
            __threadfence();
            g_gen = gen + 1;
        } else {
            while (g_gen == gen) { }
        }
    }
    __syncthreads();
    __threadfence();
}

// ---------------- persistent recurrence (x@W fused) ----------------
// 1024 tiles/step: tile tau -> s = tau&7 (ksplit), n32 = tau>>3 (32-col tile).
// tile work: 64 rows x 32 cols x (128 k of U + 64 k of x) = 0.39 MFMA.
// per-SM static lists: 12 SMs x 6 + 136 SMs x 7 = 1024; pair (bid, bid+148).
__global__ __launch_bounds__(256, 2) void recurrence(const float* __restrict__ x) {
    __shared__ float As[32][68];
    __shared__ float Bs[32][36];
    int tid = threadIdx.x;
    int tx = tid & 15, ty = tid >> 4;           // micro: 4 rows x 2 cols
    int bid = blockIdx.x;

    int sm   = (bid < NSM) ? bid : bid - NSM;
    int half = (bid < NSM) ? 0 : 1;
    int cnt   = (sm < 12) ? 6 : 7;
    int start = (sm < 12) ? 6 * sm : 72 + 7 * (sm - 12);
    int myStart, myCnt;
    if (sm >= 108) { myStart = start; myCnt = cnt; }              // single CTA
    else if (half == 0) { myStart = start; myCnt = (cnt + 1) >> 1; }
    else { myCnt = cnt >> 1; myStart = start + ((cnt + 1) >> 1); }

    int gtid = bid * 256 + tid;                  // update phase: CTAs 0..63

    for (int t = 0; t < T_; t++) {
        const float* xt = x + (size_t)t * B_ * Fdim;

        // ======== phase 1: preK[s] = (h @ U + x_t @ W)[ksplit s] tiles
        for (int it = 0; it < myCnt; it++) {
            int tau = myStart + it;
            int s = tau & 7;
            int colBase = (tau >> 3) * 32;
            int kbase = s * 128;                 // U k-range
            int xbase = s * 64;                  // x k-range
            float acc[4][2];
            #pragma unroll
            for (int i = 0; i < 4; i++) { acc[i][0] = 0.f; acc[i][1] = 0.f; }

            #pragma unroll 1
            for (int part = 0; part < 2; part++) {
                const float* Asrc = part ? xt : g_h;
                int strideA = part ? Fdim : H_;
                const float* Bsrc = part ? g_Wcat : g_Ucat;
                int kofs = part ? xbase : kbase;
                int klen = part ? 64 : 128;
                for (int k0 = 0; k0 < klen; k0 += 32) {
                    // A: 64 rows x 32 k (transposed store), 2 float4/thread
                    #pragma unroll
                    for (int i = 0; i < 2; i++) {
                        int lin = tid + i * 256;
                        int r = lin >> 3, c4 = (lin & 7) * 4;
                        float4 v = *reinterpret_cast<const float4*>(
                            &Asrc[(size_t)r * strideA + kofs + k0 + c4]);
                        As[c4 + 0][r] = v.x;
                        As[c4 + 1][r] = v.y;
                        As[c4 + 2][r] = v.z;
                        As[c4 + 3][r] = v.w;
                    }
                    {   // B: 32 k x 32 cols, 1 float4/thread
                        int kk = tid >> 3, c4 = (tid & 7) * 4;
                        float4 v = *reinterpret_cast<const float4*>(
                            &Bsrc[(size_t)(kofs + k0 + kk) * N4 + colBase + c4]);
                        *reinterpret_cast<float4*>(&Bs[kk][c4]) = v;
                    }
                    __syncthreads();
                    #pragma unroll
                    for (int kk = 0; kk < 32; kk++) {
                        float4 a = *reinterpret_cast<const float4*>(&As[kk][ty * 4]);
                        float2 b = *reinterpret_cast<const float2*>(&Bs[kk][tx * 2]);
                        acc[0][0] += a.x * b.x; acc[0][1] += a.x * b.y;
                        acc[1][0] += a.y * b.x; acc[1][1] += a.y * b.y;
                        acc[2][0] += a.z * b.x; acc[2][1] += a.z * b.y;
                        acc[3][0] += a.w * b.x; acc[3][1] += a.w * b.y;
                    }
                    __syncthreads();
                }
            }
            float* preOut = g_preK + (size_t)s * B_ * N4;
            #pragma unroll
            for (int i = 0; i < 4; i++) {
                int r = ty * 4 + i;
                float2 v = {acc[i][0], acc[i][1]};
                *reinterpret_cast<float2*>(
                    &preOut[(size_t)r * N4 + colBase + tx * 2]) = v;
            }
        }

        grid_barrier();

        // ======== phase 2: gates = bias + sum_s preK[s]; state update
        if (gtid < B_ * H_ / 4) {
            int b = gtid / (H_ / 4);
            int j = (gtid % (H_ / 4)) * 4;
            float4 pf = *reinterpret_cast<const float4*>(&g_bias4[0 * H_ + j]);
            float4 pi = *reinterpret_cast<const float4*>(&g_bias4[1 * H_ + j]);
            float4 po = *reinterpret_cast<const float4*>(&g_bias4[2 * H_ + j]);
            float4 pa = *reinterpret_cast<const float4*>(&g_bias4[3 * H_ + j]);
            #pragma unroll
            for (int sp = 0; sp < SPLITK; sp++) {
                const float* pk = g_preK + (size_t)sp * B_ * N4 + (size_t)b * N4;
                float4 vf = *reinterpret_cast<const float4*>(&pk[0 * H_ + j]);
                float4 vi = *reinterpret_cast<const float4*>(&pk[1 * H_ + j]);
                float4 vo = *reinterpret_cast<const float4*>(&pk[2 * H_ + j]);
                float4 va = *reinterpret_cast<const float4*>(&pk[3 * H_ + j]);
                pf.x += vf.x; pf.y += vf.y; pf.z += vf.z; pf.w += vf.w;
                pi.x += vi.x; pi.y += vi.y; pi.z += vi.z; pi.w += vi.w;
                po.x += vo.x; po.y += vo.y; po.z += vo.z; po.w += vo.w;
                pa.x += va.x; pa.y += va.y; pa.z += va.z; pa.w += va.w;
            }
            float fv[4] = {pf.x, pf.y, pf.z, pf.w};
            float iv[4] = {pi.x, pi.y, pi.z, pi.w};
            float ov[4] = {po.x, po.y, po.z, po.w};
            float av[4] = {pa.x, pa.y, pa.z, pa.w};
            size_t base = (size_t)b * H_ + j;
            float4 cprev = *reinterpret_cast<const float4*>(&g_c[base]);
            float cp[4] = {cprev.x, cprev.y, cprev.z, cprev.w};
            float cnv[4], hnv[4];
            #pragma unroll
            for (int q = 0; q < 4; q++) {
                float ff = 1.f / (1.f + expf(-fv[q]));
                float ii = 1.f / (1.f + expf(-iv[q]));
                float oo = 1.f / (1.f + expf(-ov[q]));
                float cc = ii * tanhf(av[q]) + ff * cp[q];
                cnv[q] = cc;
                hnv[q] = oo * tanhf(cc);
            }
            float4 cn = {cnv[0], cnv[1], cnv[2], cnv[3]};
            float4 hn = {hnv[0], hnv[1], hnv[2], hnv[3]};
            *reinterpret_cast<float4*>(&g_c[base]) = cn;
            *reinterpret_cast<float4*>(&g_h[base]) = hn;
            *reinterpret_cast<float4*>(&g_Hbuf[(size_t)t * B_ * H_ + base]) = hn;
        }

        grid_barrier();
    }
}

// ---------------- launch ----------------
extern "C" void kernel_launch(void* const* d_in, const int* in_sizes, int n_in,
                              void* d_out, int out_size) {
    const float* x    = (const float*)d_in[0];
    const float* wfxw = (const float*)d_in[1];
    const float* wfxb = (const float*)d_in[2];
    const float* wixw = (const float*)d_in[3];
    const float* wixb = (const float*)d_in[4];
    const float* woxw = (const float*)d_in[5];
    const float* woxb = (const float*)d_in[6];
    const float* wcxw = (const float*)d_in[7];
    const float* wcxb = (const float*)d_in[8];
    const float* ufhw = (const float*)d_in[9];
    const float* uihw = (const float*)d_in[10];
    const float* uohw = (const float*)d_in[11];
    const float* uchw = (const float*)d_in[12];
    const float* fcow = (const float*)d_in[13];
    const float* fcob = (const float*)d_in[14];
    float* out = (float*)d_out;

    // launch order chosen so recurrence is the 4th kernel (ncu capture slot)
    build_W<<<(Fdim * N4 + 255) / 256, 256>>>(wfxw, wixw, woxw, wcxw);      // 1
    build_U<<<(H_ * N4 + 255) / 256, 256>>>(ufhw, uihw, uohw, uchw);        // 2
    init_misc<<<(B_ * H_ + 255) / 256, 256>>>(wfxb, wixb, woxb, wcxb);      // 3
    recurrence<<<NCTA, 256>>>(x);                                           // 4
    {   // output projection: out = Hbuf @ fco_w + fco_b                    // 5
        dim3 grid((FO + 127) / 128, (T_ * B_) / 128);
        gemm_out<<<grid, 256>>>(fcow, fcob, out);
    }
}

// round 12
// speedup vs baseline: 1.4368x; 1.4368x over previous
#include <cuda_runtime.h>
#include <math.h>

// Quaternion LSTM: T=128, B=64, F=512, H=1024.
// Round 12: R7 (best, 5042us) + software pipelining only:
//   - double-buffered smem k-chunks in gemm_body and step_gemm
//     (prefetch next chunk to regs during compute; ONE sync per chunk)
//   - fullN float4 B-tile path in gemm_body (gemm_in: N=4096)
// Math order bit-identical to R7 (rel_err must stay 6.588e-7).

#define T_ 128
#define B_ 64
#define Fdim 512
#define H_ 1024
#define N4 (4 * H_)          // 4096
#define FO (Fdim + 1)        // 513
#define SPLITK 8
#define KCHUNK (H_ / SPLITK) // 128
#define NCTA 256

// ---- scratch (static device globals: allocation-free) ----
__device__ float g_Wcat[(size_t)Fdim * N4];            //  8 MB
__device__ float g_bias4[N4];
__device__ float g_Ucat[(size_t)H_ * N4];              // 16 MB
__device__ float g_G[(size_t)T_ * B_ * N4];            // 128 MB (pre-gates)
__device__ float g_preK[(size_t)SPLITK * B_ * N4];     //  8 MB
__device__ float g_h[B_ * H_];
__device__ float g_c[B_ * H_];
__device__ float g_Hbuf[(size_t)T_ * B_ * H_];         // 32 MB
__device__ unsigned g_cnt;
__device__ volatile unsigned g_gen;

__device__ const float c_sgn[16] = {
    1.f, -1.f, -1.f, -1.f,
    1.f,  1.f, -1.f,  1.f,
    1.f,  1.f,  1.f, -1.f,
    1.f, -1.f,  1.f,  1.f
};

// ---------------- init ----------------
__global__ void init_state() {
    int idx = blockIdx.x * blockDim.x + threadIdx.x;
    if (idx < B_ * H_) { g_h[idx] = 0.f; g_c[idx] = 0.f; }
    if (idx == 0) { g_cnt = 0; g_gen = 0; }
}

// ---------------- build Hamilton matrices ----------------
__global__ void build_W(const float* __restrict__ wf, const float* __restrict__ wi,
                        const float* __restrict__ wo, const float* __restrict__ wc) {
    int idx = blockIdx.x * blockDim.x + threadIdx.x;
    if (idx >= Fdim * N4) return;
    int row  = idx / N4;
    int col  = idx % N4;
    int gate = col / H_;
    int cj   = col % H_;
    int rb = row / (Fdim / 4), a = row % (Fdim / 4);
    int cb = cj / (H_ / 4),    b = cj % (H_ / 4);
    const float* w = (gate == 0) ? wf : (gate == 1) ? wi : (gate == 2) ? wo : wc;
    g_Wcat[idx] = c_sgn[cb * 4 + rb] *
                  w[((size_t)(rb ^ cb) * (Fdim / 4) + a) * (H_ / 4) + b];
}

__global__ void build_U(const float* __restrict__ uf, const float* __restrict__ ui,
                        const float* __restrict__ uo, const float* __restrict__ uc) {
    int idx = blockIdx.x * blockDim.x + threadIdx.x;
    if (idx >= H_ * N4) return;
    int row  = idx / N4;
    int col  = idx % N4;
    int gate = col / H_;
    int cj   = col % H_;
    int rb = row / (H_ / 4), a = row % (H_ / 4);
    int cb = cj / (H_ / 4),  b = cj % (H_ / 4);
    const float* w = (gate == 0) ? uf : (gate == 1) ? ui : (gate == 2) ? uo : uc;
    g_Ucat[idx] = c_sgn[cb * 4 + rb] *
                  w[((size_t)(rb ^ cb) * (H_ / 4) + a) * (H_ / 4) + b];
}

__global__ void build_bias(const float* __restrict__ bf, const float* __restrict__ bi,
                           const float* __restrict__ bo, const float* __restrict__ bc) {
    int idx = blockIdx.x * blockDim.x + threadIdx.x;
    if (idx >= N4) return;
    int gate = idx / H_, j = idx % H_;
    const float* b = (gate == 0) ? bf : (gate == 1) ? bi : (gate == 2) ? bo : bc;
    g_bias4[idx] = b[j];
}

// ---------------- generic fp32 GEMM, double-buffered ----------------
__device__ __forceinline__ void gemm_body(const float* __restrict__ A,
                                          const float* __restrict__ Bm,
                                          const float* __restrict__ bias,
                                          float* __restrict__ C,
                                          int M, int N, int K) {
    const int BM = 128, BN = 128, BK = 16;
    __shared__ __align__(16) float As[2][BK][BM];
    __shared__ __align__(16) float Bs[2][BK][BN];
    int tid = threadIdx.x;
    int tx = tid % 16, ty = tid / 16;
    int rowBase = blockIdx.y * BM;
    int colBase = blockIdx.x * BN;
    bool fullN = ((N & 3) == 0) && (colBase + BN <= N);
    float acc[8][8];
    #pragma unroll
    for (int i = 0; i < 8; i++)
        #pragma unroll
        for (int j = 0; j < 8; j++) acc[i][j] = 0.f;

    // preload chunk 0 into buffer 0
    {
        #pragma unroll
        for (int i = 0; i < 2; i++) {
            int lin = tid + i * 256;
            int r = lin >> 2, c4 = (lin & 3) * 4;
            float4 v = *reinterpret_cast<const float4*>(
                &A[(size_t)(rowBase + r) * K + c4]);
            As[0][c4 + 0][r] = v.x;
            As[0][c4 + 1][r] = v.y;
            As[0][c4 + 2][r] = v.z;
            As[0][c4 + 3][r] = v.w;
        }
        if (fullN) {
            #pragma unroll
            for (int i = 0; i < 2; i++) {
                int lin = tid + i * 256;
                int kk = lin >> 5, c4 = (lin & 31) * 4;
                float4 v = *reinterpret_cast<const float4*>(
                    &Bm[(size_t)kk * N + colBase + c4]);
                *reinterpret_cast<float4*>(&Bs[0][kk][c4]) = v;
            }
        } else {
            #pragma unroll
            for (int i = 0; i < 8; i++) {
                int lin = tid + i * 256;
                int kk = lin >> 7, n = lin & 127;
                int gn = colBase + n;
                Bs[0][kk][n] = (gn < N) ? Bm[(size_t)kk * N + gn] : 0.f;
            }
        }
    }
    __syncthreads();

    int buf = 0;
    for (int k0 = 0; k0 < K; k0 += BK) {
        bool more = (k0 + BK) < K;
        float4 pa[2];
        float4 pbv[2];
        float pbs[8];
        if (more) {
            int kn = k0 + BK;
            #pragma unroll
            for (int i = 0; i < 2; i++) {
                int lin = tid + i * 256;
                int r = lin >> 2, c4 = (lin & 3) * 4;
                pa[i] = *reinterpret_cast<const float4*>(
                    &A[(size_t)(rowBase + r) * K + kn + c4]);
            }
            if (fullN) {
                #pragma unroll
                for (int i = 0; i < 2; i++) {
                    int lin = tid + i * 256;
                    int kk = lin >> 5, c4 = (lin & 31) * 4;
                    pbv[i] = *reinterpret_cast<const float4*>(
                        &Bm[(size_t)(kn + kk) * N + colBase + c4]);
                }
            } else {
                #pragma unroll
                for (int i = 0; i < 8; i++) {
                    int lin = tid + i * 256;
                    int kk = lin >> 7, n = lin & 127;
                    int gn = colBase + n;
                    pbs[i] = (gn < N) ? Bm[(size_t)(kn + kk) * N + gn] : 0.f;
                }
            }
        }
        #pragma unroll
        for (int kk = 0; kk < BK; kk++) {
            float a[8], b[8];
            float4 a0 = *reinterpret_cast<const float4*>(&As[buf][kk][ty * 8]);
            float4 a1 = *reinterpret_cast<const float4*>(&As[buf][kk][ty * 8 + 4]);
            float4 b0 = *reinterpret_cast<const float4*>(&Bs[buf][kk][tx * 8]);
            float4 b1 = *reinterpret_cast<const float4*>(&Bs[buf][kk][tx * 8 + 4]);
            a[0]=a0.x; a[1]=a0.y; a[2]=a0.z; a[3]=a0.w;
            a[4]=a1.x; a[5]=a1.y; a[6]=a1.z; a[7]=a1.w;
            b[0]=b0.x; b[1]=b0.y; b[2]=b0.z; b[3]=b0.w;
            b[4]=b1.x; b[5]=b1.y; b[6]=b1.z; b[7]=b1.w;
            #pragma unroll
            for (int i = 0; i < 8; i++)
                #pragma unroll
                for (int j = 0; j < 8; j++)
                    acc[i][j] += a[i] * b[j];
        }
        if (more) {
            int nb = buf ^ 1;
            #pragma unroll
            for (int i = 0; i < 2; i++) {
                int lin = tid + i * 256;
                int r = lin >> 2, c4 = (lin & 3) * 4;
                As[nb][c4 + 0][r] = pa[i].x;
                As[nb][c4 + 1][r] = pa[i].y;
                As[nb][c4 + 2][r] = pa[i].z;
                As[nb][c4 + 3][r] = pa[i].w;
            }
            if (fullN) {
                #pragma unroll
                for (int i = 0; i < 2; i++) {
                    int lin = tid + i * 256;
                    int kk = lin >> 5, c4 = (lin & 31) * 4;
                    *reinterpret_cast<float4*>(&Bs[nb][kk][c4]) = pbv[i];
                }
            } else {
                #pragma unroll
                for (int i = 0; i < 8; i++) {
                    int lin = tid + i * 256;
                    int kk = lin >> 7, n = lin & 127;
                    Bs[nb][kk][n] = pbs[i];
                }
            }
        }
        __syncthreads();
        buf ^= 1;
    }
    #pragma unroll
    for (int i = 0; i < 8; i++) {
        int gm = rowBase + ty * 8 + i;
        if (gm >= M) continue;
        #pragma unroll
        for (int j = 0; j < 8; j++) {
            int gn = colBase + tx * 8 + j;
            if (gn >= N) continue;
            float v = acc[i][j];
            if (bias) v += bias[gn];
            C[(size_t)gm * N + gn] = v;
        }
    }
}

__global__ __launch_bounds__(256) void gemm_in(const float* __restrict__ x) {
    gemm_body(x, g_Wcat, g_bias4, g_G, T_ * B_, N4, Fdim);
}

__global__ __launch_bounds__(256) void gemm_out(const float* __restrict__ fw,
                                                const float* __restrict__ fb,
                                                float* __restrict__ out) {
    gemm_body(g_Hbuf, fw, fb, out, T_ * B_, FO, H_);
}

// ---------------- grid barrier (R7-proven) ----------------
__device__ __forceinline__ void grid_barrier() {
    __syncthreads();
    __threadfence();
    if (threadIdx.x == 0) {
        unsigned gen = g_gen;
        unsigned prev = atomicAdd(&g_cnt, 1u);
        if (prev == NCTA - 1) {
            g_cnt = 0;
            __threadfence();
            g_gen = gen + 1;
        } else {
            while (g_gen == gen) { }
        }
    }
    __syncthreads();
    __threadfence();
}

// ---------------- persistent recurrence (double-buffered step GEMM) ----------
__global__ __launch_bounds__(256, 2) void recurrence() {
    __shared__ __align__(16) float As[2][16][68];
    __shared__ __align__(16) float Bs[2][16][132];
    int tid = threadIdx.x;
    int tx = tid & 15, ty = tid >> 4;
    int nTile = blockIdx.x & 31;
    int s = blockIdx.x >> 5;
    int colBase = nTile * 128;
    int kbase = s * KCHUNK;
    int gtid = blockIdx.x * 256 + tid;
    float* preOut = g_preK + (size_t)s * B_ * N4;

    // A-load indices (1 float4/thread), B-load indices (2 float4/thread)
    int ar = tid >> 2, ac4 = (tid & 3) * 4;

    for (int t = 0; t < T_; t++) {
        // ======== phase 1: pre = h @ Ucat (64 x 128 tile, K chunk s)
        float acc[4][8];
        #pragma unroll
        for (int i = 0; i < 4; i++)
            #pragma unroll
            for (int j = 0; j < 8; j++) acc[i][j] = 0.f;

        {   // preload chunk 0 into buffer 0
            float4 v = *reinterpret_cast<const float4*>(
                &g_h[(size_t)ar * H_ + kbase + ac4]);
            As[0][ac4 + 0][ar] = v.x;
            As[0][ac4 + 1][ar] = v.y;
            As[0][ac4 + 2][ar] = v.z;
            As[0][ac4 + 3][ar] = v.w;
            #pragma unroll
            for (int i = 0; i < 2; i++) {
                int lin = tid + i * 256;
                int kk = lin >> 5, c4 = (lin & 31) * 4;
                float4 bv = *reinterpret_cast<const float4*>(
                    &g_Ucat[(size_t)(kbase + kk) * N4 + colBase + c4]);
                *reinterpret_cast<float4*>(&Bs[0][kk][c4]) = bv;
            }
        }
        __syncthreads();

        int buf = 0;
        for (int k0 = 0; k0 < KCHUNK; k0 += 16) {
            bool more = (k0 + 16) < KCHUNK;
            float4 pa;
            float4 pb[2];
            if (more) {
                int kn = kbase + k0 + 16;
                pa = *reinterpret_cast<const float4*>(
                    &g_h[(size_t)ar * H_ + kn + ac4]);
                #pragma unroll
                for (int i = 0; i < 2; i++) {
                    int lin = tid + i * 256;
                    int kk = lin >> 5, c4 = (lin & 31) * 4;
                    pb[i] = *reinterpret_cast<const float4*>(
                        &g_Ucat[(size_t)(kn + kk) * N4 + colBase + c4]);
                }
            }
            #pragma unroll
            for (int kk = 0; kk < 16; kk++) {
                float4 av = *reinterpret_cast<const float4*>(&As[buf][kk][ty * 4]);
                float4 b0 = *reinterpret_cast<const float4*>(&Bs[buf][kk][tx * 8]);
                float4 b1 = *reinterpret_cast<const float4*>(&Bs[buf][kk][tx * 8 + 4]);
                float a[4] = {av.x, av.y, av.z, av.w};
                float b[8] = {b0.x, b0.y, b0.z, b0.w, b1.x, b1.y, b1.z, b1.w};
                #pragma unroll
                for (int i = 0; i < 4; i++)
                    #pragma unroll
                    for (int j = 0; j < 8; j++)
                        acc[i][j] += a[i] * b[j];
            }
            if (more) {
                int nb = buf ^ 1;
                As[nb][ac4 + 0][ar] = pa.x;
                As[nb][ac4 + 1][ar] = pa.y;
                As[nb][ac4 + 2][ar] = pa.z;
                As[nb][ac4 + 3][ar] = pa.w;
                #pragma unroll
                for (int i = 0; i < 2; i++) {
                    int lin = tid + i * 256;
                    int kk = lin >> 5, c4 = (lin & 31) * 4;
                    *reinterpret_cast<float4*>(&Bs[nb][kk][c4]) = pb[i];
                }
            }
            __syncthreads();
            buf ^= 1;
        }
        #pragma unroll
        for (int i = 0; i < 4; i++) {
            int r = ty * 4 + i;
            float4 v0 = {acc[i][0], acc[i][1], acc[i][2], acc[i][3]};
            float4 v1 = {acc[i][4], acc[i][5], acc[i][6], acc[i][7]};
            *reinterpret_cast<float4*>(&preOut[(size_t)r * N4 + colBase + tx * 8])     = v0;
            *reinterpret_cast<float4*>(&preOut[(size_t)r * N4 + colBase + tx * 8 + 4]) = v1;
        }

        grid_barrier();

        // ======== phase 2: gates + state update (threads 0..16383 active)
        if (gtid < B_ * H_ / 4) {
            int b = gtid / (H_ / 4);
            int j = (gtid % (H_ / 4)) * 4;
            const float* Gt = g_G + (size_t)((size_t)t * B_ + b) * N4;
            float4 pf = *reinterpret_cast<const float4*>(&Gt[0 * H_ + j]);
            float4 pi = *reinterpret_cast<const float4*>(&Gt[1 * H_ + j]);
            float4 po = *reinterpret_cast<const float4*>(&Gt[2 * H_ + j]);
            float4 pa = *reinterpret_cast<const float4*>(&Gt[3 * H_ + j]);
            #pragma unroll
            for (int sp = 0; sp < SPLITK; sp++) {
                const float* pk = g_preK + (size_t)sp * B_ * N4 + (size_t)b * N4;
                float4 vf = *reinterpret_cast<const float4*>(&pk[0 * H_ + j]);
                float4 vi = *reinterpret_cast<const float4*>(&pk[1 * H_ + j]);
                float4 vo = *reinterpret_cast<const float4*>(&pk[2 * H_ + j]);
                float4 va = *reinterpret_cast<const float4*>(&pk[3 * H_ + j]);
                pf.x += vf.x; pf.y += vf.y; pf.z += vf.z; pf.w += vf.w;
                pi.x += vi.x; pi.y += vi.y; pi.z += vi.z; pi.w += vi.w;
                po.x += vo.x; po.y += vo.y; po.z += vo.z; po.w += vo.w;
                pa.x += va.x; pa.y += va.y; pa.z += va.z; pa.w += va.w;
            }
            float fv[4] = {pf.x, pf.y, pf.z, pf.w};
            float iv[4] = {pi.x, pi.y, pi.z, pi.w};
            float ov[4] = {po.x, po.y, po.z, po.w};
            float av[4] = {pa.x, pa.y, pa.z, pa.w};
            size_t base = (size_t)b * H_ + j;
            float4 cprev = *reinterpret_cast<const float4*>(&g_c[base]);
            float cp[4] = {cprev.x, cprev.y, cprev.z, cprev.w};
            float cnv[4], hnv[4];
            #pragma unroll
            for (int q = 0; q < 4; q++) {
                float ff = 1.f / (1.f + expf(-fv[q]));
                float ii = 1.f / (1.f + expf(-iv[q]));
                float oo = 1.f / (1.f + expf(-ov[q]));
                float cc = ii * tanhf(av[q]) + ff * cp[q];
                cnv[q] = cc;
                hnv[q] = oo * tanhf(cc);
            }
            float4 cn = {cnv[0], cnv[1], cnv[2], cnv[3]};
            float4 hn = {hnv[0], hnv[1], hnv[2], hnv[3]};
            *reinterpret_cast<float4*>(&g_c[base]) = cn;
            *reinterpret_cast<float4*>(&g_h[base]) = hn;
            *reinterpret_cast<float4*>(&g_Hbuf[(size_t)t * B_ * H_ + base]) = hn;
        }

        grid_barrier();
    }
}

// ---------------- launch ----------------
extern "C" void kernel_launch(void* const* d_in, const int* in_sizes, int n_in,
                              void* d_out, int out_size) {
    const float* x    = (const float*)d_in[0];
    const float* wfxw = (const float*)d_in[1];
    const float* wfxb = (const float*)d_in[2];
    const float* wixw = (const float*)d_in[3];
    const float* wixb = (const float*)d_in[4];
    const float* woxw = (const float*)d_in[5];
    const float* woxb = (const float*)d_in[6];
    const float* wcxw = (const float*)d_in[7];
    const float* wcxb = (const float*)d_in[8];
    const float* ufhw = (const float*)d_in[9];
    const float* uihw = (const float*)d_in[10];
    const float* uohw = (const float*)d_in[11];
    const float* uchw = (const float*)d_in[12];
    const float* fcow = (const float*)d_in[13];
    const float* fcob = (const float*)d_in[14];
    float* out = (float*)d_out;

    init_state<<<(B_ * H_ + 255) / 256, 256>>>();
    build_W<<<(Fdim * N4 + 255) / 256, 256>>>(wfxw, wixw, woxw, wcxw);
    build_bias<<<(N4 + 255) / 256, 256>>>(wfxb, wixb, woxb, wcxb);
    build_U<<<(H_ * N4 + 255) / 256, 256>>>(ufhw, uihw, uohw, uchw);

    {   // input projections: G = x @ Wcat + bias
        dim3 grid(N4 / 128, (T_ * B_) / 128);
        gemm_in<<<grid, 256>>>(x);
    }

    recurrence<<<NCTA, 256>>>();

    {   // output projection: out = Hbuf @ fco_w + fco_b
        dim3 grid((FO + 127) / 128, (T_ * B_) / 128);
        gemm_out<<<grid, 256>>>(fcow, fcob, out);
    }
}